// round 11
// baseline (speedup 1.0000x reference)
#include <cuda_runtime.h>
#include <cuda_fp16.h>
#include <math_constants.h>

#define BB 16
#define KK 256
#define ZZ 128
#define HH 128
#define BK (BB*KK)

typedef unsigned long long u64;

#define FMA2(d, a, b, c) \
  asm("fma.rn.f32x2 %0, %1, %2, %3;" : "=l"(d) : "l"(a), "l"(b), "l"(c))

__device__ __forceinline__ u64 pack2(float lo, float hi) {
  u64 r;
  asm("mov.b64 %0, {%1, %2};" : "=l"(r) : "f"(lo), "f"(hi));
  return r;
}
__device__ __forceinline__ float sum2(u64 p) {
  float lo, hi;
  asm("mov.b64 {%0, %1}, %2;" : "=f"(lo), "=f"(hi) : "l"(p));
  return lo + hi;
}

// scratch (allocation-free: __device__ globals)
__device__ float   g_m1[BK*ZZ];
__device__ float   g_m2[BK*ZZ];
__device__ __half2 g_m2h[BK*64];   // fp16 mirror of m2 for the max pass
__device__ float   g_mm[BK*ZZ];
// k-pair-packed transposed weights: WT[kp*NC + c] = {W[c][2kp], W[c][2kp+1]}
__device__ u64 g_wt1[64 * ZZ];     // [64 kp][128 c]
__device__ u64 g_wt2[64 * ZZ];     // [64 kp][128 c]
__device__ u64 g_wtu[128 * HH];    // [128 kp][128 c]

extern __shared__ __align__(16) u64 dynsmem[];

// ---------------------------------------------------------------------------
// Pack kernel: k-pair-packed transposed weights. grid=128, block=256.
// ---------------------------------------------------------------------------
__global__ __launch_bounds__(256) void pack_kernel(
    const float* __restrict__ W1, const float* __restrict__ W2,
    const float* __restrict__ Wu) {
  const int idx = blockIdx.x * 256 + threadIdx.x;
  if (idx < 8192) {
    const int kp = idx >> 7, c = idx & 127;
    g_wt1[kp * ZZ + c] = pack2(W1[c * ZZ + 2*kp], W1[c * ZZ + 2*kp + 1]);
  } else if (idx < 16384) {
    const int l = idx - 8192;
    const int kp = l >> 7, c = l & 127;
    g_wt2[kp * ZZ + c] = pack2(W2[c * ZZ + 2*kp], W2[c * ZZ + 2*kp + 1]);
  } else {
    const int l = idx - 16384;
    const int kp = l >> 7, c = l & 127;
    g_wtu[kp * HH + c] = pack2(Wu[c * (2*ZZ) + 2*kp], Wu[c * (2*ZZ) + 2*kp + 1]);
  }
}

// ---------------------------------------------------------------------------
// Kernel 1: y = x @ W^T + b, both weight sets. grid=(BK/32, 2 wsets), block=256.
// smem: sw[64kp][128c] u64 (64KB) + sx[32r][128k] fp32 (16KB) = 80KB -> 2 blk/SM.
// Warp = 8 rows (rg=warp>>1) x 64 cols (cs=warp&1); lane owns 2 cols.
// Prefetched weights (LDS.128), batched broadcast x loads.
// ---------------------------------------------------------------------------
__global__ __launch_bounds__(256, 2) void lin_kernel(
    const float* __restrict__ z,
    const float* __restrict__ b1, const float* __restrict__ b2) {
  const u64*   WT   = blockIdx.y ? g_wt2 : g_wt1;
  const float* bias = blockIdx.y ? b2 : b1;
  float*       y    = blockIdx.y ? g_m2 : g_m1;

  u64*   sw = dynsmem;                      // [64][128]
  float* sx = (float*)(dynsmem + 64 * ZZ);  // [32][128]

  const int tid  = threadIdx.x;
  const int row0 = blockIdx.x * 32;

  // stage packed weights (64KB, coalesced 16B)
  {
    ulonglong2*       d = (ulonglong2*)sw;
    const ulonglong2* s = (const ulonglong2*)WT;
#pragma unroll
    for (int i = 0; i < 16; i++) d[i * 256 + tid] = s[i * 256 + tid];
  }
  // stage raw activations (1024 float4)
  {
    float4*       d = (float4*)sx;
    const float4* s = (const float4*)(z + row0 * ZZ);
#pragma unroll
    for (int i = 0; i < 4; i++) d[i * 256 + tid] = s[i * 256 + tid];
  }
  __syncthreads();

  const int lane = tid & 31;
  const int warp = tid >> 5;
  const int rg   = warp >> 1;               // row group 0..3 (8 rows)
  const int cs   = warp & 1;                // col half (64 cols)
  const float* xb = sx + rg * 8 * ZZ;
  const u64*   wb = sw + cs * 64 + lane * 2;

  u64 acc[8][2];
#pragma unroll
  for (int r = 0; r < 8; r++) { acc[r][0] = 0ULL; acc[r][1] = 0ULL; }

  ulonglong2 wa = *(const ulonglong2*)(wb);
  ulonglong2 wc = *(const ulonglong2*)(wb + ZZ);

#pragma unroll 4
  for (int kp2 = 0; kp2 < 32; kp2++) {      // 4 k per iter
    const int nxt = (kp2 + 1) & 31;
    const ulonglong2 wa_n = *(const ulonglong2*)(wb + (2*nxt)     * ZZ);
    const ulonglong2 wc_n = *(const ulonglong2*)(wb + (2*nxt + 1) * ZZ);
    ulonglong2 xq[8];
#pragma unroll
    for (int r = 0; r < 8; r++)
      xq[r] = *(const ulonglong2*)(xb + r * ZZ + 4*kp2);   // broadcast
#pragma unroll
    for (int r = 0; r < 8; r++) {
      FMA2(acc[r][0], wa.x, xq[r].x, acc[r][0]);
      FMA2(acc[r][1], wa.y, xq[r].x, acc[r][1]);
      FMA2(acc[r][0], wc.x, xq[r].y, acc[r][0]);
      FMA2(acc[r][1], wc.y, xq[r].y, acc[r][1]);
    }
    wa = wa_n; wc = wc_n;
  }

  const float2 bv = ((const float2*)bias)[cs * 32 + lane];
  const int wr = blockIdx.y;
#pragma unroll
  for (int r = 0; r < 8; r++) {
    const int row = row0 + rg * 8 + r;
    float2 o;
    o.x = sum2(acc[r][0]) + bv.x;
    o.y = sum2(acc[r][1]) + bv.y;
    ((float2*)(y + row * ZZ + cs * 64))[lane] = o;
    if (wr) g_m2h[row * 64 + cs * 32 + lane] = __float22half2_rn(o);
  }
}

// ---------------------------------------------------------------------------
// Kernel 2: masked neighbor max (fp16) + relu(m1 + max) -> g_mm (fp32)
// grid = (K/16, B), block = 512 (warp = one destination node i).
// smem: 64KB fp16 m2 tile (dynamic) + 4KB adjacency bytes (static).
// ---------------------------------------------------------------------------
__global__ __launch_bounds__(512) void maxagg_kernel(const int* __restrict__ P) {
  __shared__ unsigned char s_adj[KK * 16];  // 4KB

  uint2* sh = (uint2*)dynsmem;              // [256 rows][32 lanes] uint2
  const int b   = blockIdx.y;
  const int i0  = blockIdx.x * 16;
  const int tid = threadIdx.x;
  const int* Pb = P + b * KK * KK;

  {
    uint4*       d = (uint4*)sh;
    const uint4* s = (const uint4*)(g_m2h + (size_t)b * KK * 64);
#pragma unroll
    for (int c = 0; c < 8; c++) d[c * 512 + tid] = s[c * 512 + tid];
  }
#pragma unroll
  for (int c = 0; c < 8; c++) {
    const int idx = c * 512 + tid;          // 0..4095
    s_adj[idx] = (Pb[(idx >> 4) * KK + i0 + (idx & 15)] != 0);
  }
  __syncthreads();

  const int warp = tid >> 5;
  const int lane = tid & 31;
  const int i    = i0 + warp;

  unsigned words[8];
#pragma unroll
  for (int wd = 0; wd < 8; wd++) {
    const unsigned pv = s_adj[(wd * 32 + lane) * 16 + warp];
    words[wd] = __ballot_sync(0xFFFFFFFFu, pv != 0);
  }

  const __half2 ninf = __half2half2(__ushort_as_half(0xFC00));  // -inf
  __half2 a0 = ninf, a1 = ninf;
  const uint2* row = sh + lane;

#pragma unroll
  for (int wd = 0; wd < 8; wd++) {
    unsigned word = words[wd];
    const int base = wd * 32;
    while (word) {                          // warp-uniform: only active neighbors
      const int j = base + __ffs((int)word) - 1;
      word &= word - 1;
      const uint2 v = row[j * 32];          // 256B/warp = 2 wavefronts
      a0 = __hmax2(a0, *(const __half2*)&v.x);
      a1 = __hmax2(a1, *(const __half2*)&v.y);
    }
  }

  const float2 f0 = __half22float2(a0);
  const float2 f1 = __half22float2(a1);
  const int ri = (b * KK + i) * ZZ + lane * 4;
  const float4 m1 = *(const float4*)(g_m1 + ri);
  float4 o;
  o.x = fmaxf(m1.x + f0.x, 0.0f);
  o.y = fmaxf(m1.y + f0.y, 0.0f);
  o.z = fmaxf(m1.z + f1.x, 0.0f);
  o.w = fmaxf(m1.w + f1.y, 0.0f);
  *(float4*)(g_mm + ri) = o;
}

// ---------------------------------------------------------------------------
// Kernel 3: out = relu([z, m] @ Wu^T + bu). grid=(BK/32, 2 colhalf), block=256.
// smem: sw[128kp][64c] u64 (64KB) + sx[32r][256k] fp32 (32KB) = 96KB -> 2 blk/SM.
// Warp = 8 rows (rg=warp>>1) x 32 cols (cs=warp&1); lane owns 1 col (LDS.64 w).
// ---------------------------------------------------------------------------
__global__ __launch_bounds__(256, 2) void out_kernel(
    const float* __restrict__ z,
    const float* __restrict__ bu, float* __restrict__ out) {
  u64*   sw = dynsmem;                      // [128][64]
  float* sx = (float*)(dynsmem + 128 * 64); // [32][256]

  const int tid  = threadIdx.x;
  const int h    = blockIdx.y;              // column half (64 cols)
  const int row0 = blockIdx.x * 32;

  // stage weight half (8192 u64, coalesced 512B runs)
#pragma unroll
  for (int i = 0; i < 32; i++) {
    const int idx = i * 256 + tid;
    const int kp = idx >> 6, cl = idx & 63;
    sw[idx] = g_wtu[kp * HH + h * 64 + cl];
  }
  // stage raw [z | m] tile: 32 rows x 256 floats (1024 float4 per source)
  {
    const float4* zg = (const float4*)(z + row0 * ZZ);
    const float4* mg = (const float4*)(g_mm + row0 * ZZ);
#pragma unroll
    for (int i = 0; i < 4; i++) {
      const int idx = i * 256 + tid;        // 0..1023: row r, chunk c of 32
      const int r = idx >> 5, c = idx & 31;
      ((float4*)sx)[r * 64 + c]      = zg[idx];
      ((float4*)sx)[r * 64 + 32 + c] = mg[idx];
    }
  }
  __syncthreads();

  const int lane = tid & 31;
  const int warp = tid >> 5;
  const int rg   = warp >> 1;               // row group 0..3 (8 rows)
  const int cs   = warp & 1;                // col sub (32 cols)
  const float* xb = sx + rg * 8 * 256;
  const u64*   wb = sw + cs * 32 + lane;

  u64 acc[8];
#pragma unroll
  for (int r = 0; r < 8; r++) acc[r] = 0ULL;

  u64 wa = wb[0];
  u64 wc = wb[64];

#pragma unroll 4
  for (int kp2 = 0; kp2 < 64; kp2++) {      // 4 k per iter
    const int nxt = (kp2 + 1) & 63;
    const u64 wa_n = wb[(2*nxt)     * 64];
    const u64 wc_n = wb[(2*nxt + 1) * 64];
    ulonglong2 xq[8];
#pragma unroll
    for (int r = 0; r < 8; r++)
      xq[r] = *(const ulonglong2*)(xb + r * 256 + 4*kp2);  // broadcast
#pragma unroll
    for (int r = 0; r < 8; r++) {
      FMA2(acc[r], wa, xq[r].x, acc[r]);
      FMA2(acc[r], wc, xq[r].y, acc[r]);
    }
    wa = wa_n; wc = wc_n;
  }

  const float bz = bu[h * 64 + cs * 32 + lane];
#pragma unroll
  for (int r = 0; r < 8; r++) {
    const float o = fmaxf(sum2(acc[r]) + bz, 0.0f);
    out[(row0 + rg * 8 + r) * HH + h * 64 + cs * 32 + lane] = o;
  }
}

// ---------------------------------------------------------------------------
extern "C" void kernel_launch(void* const* d_in, const int* in_sizes, int n_in,
                              void* d_out, int out_size) {
  const float* z  = (const float*)d_in[0];
  const int*   P  = (const int*)  d_in[1];
  const float* W1 = (const float*)d_in[2];
  const float* b1 = (const float*)d_in[3];
  const float* W2 = (const float*)d_in[4];
  const float* b2 = (const float*)d_in[5];
  const float* Wu = (const float*)d_in[6];
  const float* bu = (const float*)d_in[7];
  float* out = (float*)d_out;

  (void)cudaFuncSetAttribute(lin_kernel, cudaFuncAttributeMaxDynamicSharedMemorySize, 81920);
  (void)cudaFuncSetAttribute(maxagg_kernel, cudaFuncAttributeMaxDynamicSharedMemorySize, 65536);
  (void)cudaFuncSetAttribute(out_kernel, cudaFuncAttributeMaxDynamicSharedMemorySize, 98304);

  pack_kernel<<<128, 256>>>(W1, W2, Wu);
  lin_kernel<<<dim3(BK / 32, 2), 256, 81920>>>(z, b1, b2);
  maxagg_kernel<<<dim3(KK / 16, BB), 512, 65536>>>(P);
  out_kernel<<<dim3(BK / 32, 2), 256, 98304>>>(z, bu, out);
}

// round 13
// speedup vs baseline: 1.0945x; 1.0945x over previous
#include <cuda_runtime.h>
#include <cuda_fp16.h>
#include <math_constants.h>

#define BB 16
#define KK 256
#define ZZ 128
#define HH 128
#define BK (BB*KK)

typedef unsigned long long u64;

#define FMA2(d, a, b, c) \
  asm("fma.rn.f32x2 %0, %1, %2, %3;" : "=l"(d) : "l"(a), "l"(b), "l"(c))

__device__ __forceinline__ u64 pack2(float lo, float hi) {
  u64 r;
  asm("mov.b64 %0, {%1, %2};" : "=l"(r) : "f"(lo), "f"(hi));
  return r;
}
__device__ __forceinline__ float sum2(u64 p) {
  float lo, hi;
  asm("mov.b64 {%0, %1}, %2;" : "=f"(lo), "=f"(hi) : "l"(p));
  return lo + hi;
}

// scratch (allocation-free: __device__ globals)
__device__ float   g_m1[BK*ZZ];
__device__ float   g_m2[BK*ZZ];
__device__ __half2 g_m2h[BK*64];   // fp16 mirror of m2 for the max pass
__device__ float   g_mm[BK*ZZ];
// k-pair-packed transposed weights: WT[kp*NC + c] = {W[c][2kp], W[c][2kp+1]}
__device__ u64 g_wt1[64 * ZZ];     // [64 kp][128 c]
__device__ u64 g_wt2[64 * ZZ];     // [64 kp][128 c]
__device__ u64 g_wtu[128 * HH];    // [128 kp][128 c]

extern __shared__ __align__(16) u64 dynsmem[];

// ---------------------------------------------------------------------------
// Pack kernel: k-pair-packed transposed weights. grid=128, block=256.
// ---------------------------------------------------------------------------
__global__ __launch_bounds__(256) void pack_kernel(
    const float* __restrict__ W1, const float* __restrict__ W2,
    const float* __restrict__ Wu) {
  const int idx = blockIdx.x * 256 + threadIdx.x;
  if (idx < 8192) {
    const int kp = idx >> 7, c = idx & 127;
    g_wt1[kp * ZZ + c] = pack2(W1[c * ZZ + 2*kp], W1[c * ZZ + 2*kp + 1]);
  } else if (idx < 16384) {
    const int l = idx - 8192;
    const int kp = l >> 7, c = l & 127;
    g_wt2[kp * ZZ + c] = pack2(W2[c * ZZ + 2*kp], W2[c * ZZ + 2*kp + 1]);
  } else {
    const int l = idx - 16384;
    const int kp = l >> 7, c = l & 127;
    g_wtu[kp * HH + c] = pack2(Wu[c * (2*ZZ) + 2*kp], Wu[c * (2*ZZ) + 2*kp + 1]);
  }
}

// ---------------------------------------------------------------------------
// Kernel 1: y = x @ W^T + b, both weight sets. grid=(BK/64, 2 wsets), block=512.
// smem: sw[64kp][128c] u64 (64KB) + sx[64r][128k] fp32 (32KB) = 96KB.
// Warp = 8 rows x 64 cols (rg=warp>>1, h=warp&1); lane owns 2 cols.
// Software-pipelined: weights + half-group x loads prefetched.
// ---------------------------------------------------------------------------
__global__ __launch_bounds__(512) void lin_kernel(
    const float* __restrict__ z,
    const float* __restrict__ b1, const float* __restrict__ b2) {
  const u64*   WT   = blockIdx.y ? g_wt2 : g_wt1;
  const float* bias = blockIdx.y ? b2 : b1;
  float*       y    = blockIdx.y ? g_m2 : g_m1;

  u64*   sw = dynsmem;                      // [64][128]
  float* sx = (float*)(dynsmem + 64 * ZZ);  // [64][128]

  const int tid  = threadIdx.x;
  const int row0 = blockIdx.x * 64;

  // stage packed weights (64KB, coalesced 16B)
  {
    ulonglong2*       d = (ulonglong2*)sw;
    const ulonglong2* s = (const ulonglong2*)WT;
#pragma unroll
    for (int i = 0; i < 8; i++) d[i * 512 + tid] = s[i * 512 + tid];
  }
  // stage raw activations (2048 float4)
  {
    float4*       d = (float4*)sx;
    const float4* s = (const float4*)(z + row0 * ZZ);
#pragma unroll
    for (int i = 0; i < 4; i++) d[i * 512 + tid] = s[i * 512 + tid];
  }
  __syncthreads();

  const int lane = tid & 31;
  const int warp = tid >> 5;
  const int rg   = warp >> 1;               // row group 0..7 (8 rows)
  const int h    = warp & 1;                // col half
  const float* xb = sx + rg * 8 * ZZ;
  const u64*   wb = sw + h * 64 + lane * 2;

  u64 acc[8][2];
#pragma unroll
  for (int r = 0; r < 8; r++) { acc[r][0] = 0ULL; acc[r][1] = 0ULL; }

  ulonglong2 wa = *(const ulonglong2*)(wb);
  ulonglong2 wc = *(const ulonglong2*)(wb + ZZ);
  ulonglong2 xqa[4], xqb[4];
#pragma unroll
  for (int r = 0; r < 4; r++)
    xqa[r] = *(const ulonglong2*)(xb + r * ZZ);       // rows 0-3, kp2=0

#pragma unroll 4
  for (int kp2 = 0; kp2 < 32; kp2++) {      // 4 k per iter
    const int nxt = (kp2 + 1) & 31;
    const ulonglong2 wa_n = *(const ulonglong2*)(wb + (2*nxt)     * ZZ);
    const ulonglong2 wc_n = *(const ulonglong2*)(wb + (2*nxt + 1) * ZZ);
    // load rows 4-7 (this kp2) while rows 0-3 FMAs run
#pragma unroll
    for (int r = 0; r < 4; r++)
      xqb[r] = *(const ulonglong2*)(xb + (r + 4) * ZZ + 4*kp2);
#pragma unroll
    for (int r = 0; r < 4; r++) {
      FMA2(acc[r][0], wa.x, xqa[r].x, acc[r][0]);
      FMA2(acc[r][1], wa.y, xqa[r].x, acc[r][1]);
      FMA2(acc[r][0], wc.x, xqa[r].y, acc[r][0]);
      FMA2(acc[r][1], wc.y, xqa[r].y, acc[r][1]);
    }
    // load rows 0-3 (next kp2) while rows 4-7 FMAs run
#pragma unroll
    for (int r = 0; r < 4; r++)
      xqa[r] = *(const ulonglong2*)(xb + r * ZZ + 4*nxt);
#pragma unroll
    for (int r = 0; r < 4; r++) {
      FMA2(acc[r+4][0], wa.x, xqb[r].x, acc[r+4][0]);
      FMA2(acc[r+4][1], wa.y, xqb[r].x, acc[r+4][1]);
      FMA2(acc[r+4][0], wc.x, xqb[r].y, acc[r+4][0]);
      FMA2(acc[r+4][1], wc.y, xqb[r].y, acc[r+4][1]);
    }
    wa = wa_n; wc = wc_n;
  }

  const float2 bv = ((const float2*)bias)[h * 32 + lane];
  const int wr = blockIdx.y;
#pragma unroll
  for (int r = 0; r < 8; r++) {
    const int row = row0 + rg * 8 + r;
    float2 o;
    o.x = sum2(acc[r][0]) + bv.x;
    o.y = sum2(acc[r][1]) + bv.y;
    ((float2*)(y + row * ZZ + h * 64))[lane] = o;
    if (wr) g_m2h[row * 64 + h * 32 + lane] = __float22half2_rn(o);
  }
}

// ---------------------------------------------------------------------------
// Kernel 2: masked neighbor max (fp16) + relu(m1 + max) -> g_mm (fp32)
// grid = (K/16, B), block = 512 (warp = one destination node i).
// smem: 64KB fp16 m2 tile (dynamic) + 4KB adjacency bytes (static).
// ---------------------------------------------------------------------------
__global__ __launch_bounds__(512) void maxagg_kernel(const int* __restrict__ P) {
  __shared__ unsigned char s_adj[KK * 16];  // 4KB

  uint2* sh = (uint2*)dynsmem;              // [256 rows][32 lanes] uint2
  const int b   = blockIdx.y;
  const int i0  = blockIdx.x * 16;
  const int tid = threadIdx.x;
  const int* Pb = P + b * KK * KK;

  {
    uint4*       d = (uint4*)sh;
    const uint4* s = (const uint4*)(g_m2h + (size_t)b * KK * 64);
#pragma unroll
    for (int c = 0; c < 8; c++) d[c * 512 + tid] = s[c * 512 + tid];
  }
#pragma unroll
  for (int c = 0; c < 8; c++) {
    const int idx = c * 512 + tid;          // 0..4095
    s_adj[idx] = (Pb[(idx >> 4) * KK + i0 + (idx & 15)] != 0);
  }
  __syncthreads();

  const int warp = tid >> 5;
  const int lane = tid & 31;
  const int i    = i0 + warp;

  unsigned words[8];
#pragma unroll
  for (int wd = 0; wd < 8; wd++) {
    const unsigned pv = s_adj[(wd * 32 + lane) * 16 + warp];
    words[wd] = __ballot_sync(0xFFFFFFFFu, pv != 0);
  }

  const __half2 ninf = __half2half2(__ushort_as_half(0xFC00));  // -inf
  __half2 a0 = ninf, a1 = ninf;
  const uint2* row = sh + lane;

#pragma unroll
  for (int wd = 0; wd < 8; wd++) {
    unsigned word = words[wd];
    const int base = wd * 32;
    while (word) {                          // warp-uniform: only active neighbors
      const int j = base + __ffs((int)word) - 1;
      word &= word - 1;
      const uint2 v = row[j * 32];          // 256B/warp = 2 wavefronts
      a0 = __hmax2(a0, *(const __half2*)&v.x);
      a1 = __hmax2(a1, *(const __half2*)&v.y);
    }
  }

  const float2 f0 = __half22float2(a0);
  const float2 f1 = __half22float2(a1);
  const int ri = (b * KK + i) * ZZ + lane * 4;
  const float4 m1 = *(const float4*)(g_m1 + ri);
  float4 o;
  o.x = fmaxf(m1.x + f0.x, 0.0f);
  o.y = fmaxf(m1.y + f0.y, 0.0f);
  o.z = fmaxf(m1.z + f1.x, 0.0f);
  o.w = fmaxf(m1.w + f1.y, 0.0f);
  *(float4*)(g_mm + ri) = o;
}

// ---------------------------------------------------------------------------
// Kernel 3: out = relu([z, m] @ Wu^T + bu). grid=(BK/64, 2 colhalf), block=256.
// smem: sw[128kp][64c] u64 (64KB) + sx[64r][256k] fp32 (64KB) = 128KB.
// Warp = 8 rows x 64 cols; lane owns 2 cols. Pipelined weights + half-group x.
// ---------------------------------------------------------------------------
__global__ __launch_bounds__(256) void out_kernel(
    const float* __restrict__ z,
    const float* __restrict__ bu, float* __restrict__ out) {
  u64*   sw = dynsmem;                      // [128][64]
  float* sx = (float*)(dynsmem + 128 * 64); // [64][256]

  const int tid  = threadIdx.x;
  const int h    = blockIdx.y;              // column half (64 cols)
  const int row0 = blockIdx.x * 64;

  // stage weight half (8192 u64, coalesced 512B runs)
#pragma unroll
  for (int i = 0; i < 32; i++) {
    const int idx = i * 256 + tid;
    const int kp = idx >> 6, cl = idx & 63;
    sw[idx] = g_wtu[kp * HH + h * 64 + cl];
  }
  // stage raw [z | m] tile: 64 rows x 256 floats (2048 float4 per source)
  {
    const float4* zg = (const float4*)(z + row0 * ZZ);
    const float4* mg = (const float4*)(g_mm + row0 * ZZ);
#pragma unroll
    for (int i = 0; i < 8; i++) {
      const int idx = i * 256 + tid;        // 0..2047: row r, chunk c of 32
      const int r = idx >> 5, c = idx & 31;
      ((float4*)sx)[r * 64 + c]      = zg[idx];
      ((float4*)sx)[r * 64 + 32 + c] = mg[idx];
    }
  }
  __syncthreads();

  const int lane = tid & 31;
  const int warp = tid >> 5;                // row group 0..7 (8 rows)
  const float* xb = sx + warp * 8 * 256;
  const u64*   wb = sw + lane * 2;

  u64 acc[8][2];
#pragma unroll
  for (int r = 0; r < 8; r++) { acc[r][0] = 0ULL; acc[r][1] = 0ULL; }

  ulonglong2 wa = *(const ulonglong2*)(wb);
  ulonglong2 wc = *(const ulonglong2*)(wb + 64);
  ulonglong2 xqa[4], xqb[4];
#pragma unroll
  for (int r = 0; r < 4; r++)
    xqa[r] = *(const ulonglong2*)(xb + r * 256);      // rows 0-3, kp2=0

#pragma unroll 2
  for (int kp2 = 0; kp2 < 64; kp2++) {      // 4 k per iter
    const int nxt = (kp2 + 1) & 63;
    const ulonglong2 wa_n = *(const ulonglong2*)(wb + (2*nxt)     * 64);
    const ulonglong2 wc_n = *(const ulonglong2*)(wb + (2*nxt + 1) * 64);
#pragma unroll
    for (int r = 0; r < 4; r++)
      xqb[r] = *(const ulonglong2*)(xb + (r + 4) * 256 + 4*kp2);
#pragma unroll
    for (int r = 0; r < 4; r++) {
      FMA2(acc[r][0], wa.x, xqa[r].x, acc[r][0]);
      FMA2(acc[r][1], wa.y, xqa[r].x, acc[r][1]);
      FMA2(acc[r][0], wc.x, xqa[r].y, acc[r][0]);
      FMA2(acc[r][1], wc.y, xqa[r].y, acc[r][1]);
    }
#pragma unroll
    for (int r = 0; r < 4; r++)
      xqa[r] = *(const ulonglong2*)(xb + r * 256 + 4*nxt);
#pragma unroll
    for (int r = 0; r < 4; r++) {
      FMA2(acc[r+4][0], wa.x, xqb[r].x, acc[r+4][0]);
      FMA2(acc[r+4][1], wa.y, xqb[r].x, acc[r+4][1]);
      FMA2(acc[r+4][0], wc.x, xqb[r].y, acc[r+4][0]);
      FMA2(acc[r+4][1], wc.y, xqb[r].y, acc[r+4][1]);
    }
    wa = wa_n; wc = wc_n;
  }

  const float2 bv = ((const float2*)bu)[h * 32 + lane];
#pragma unroll
  for (int r = 0; r < 8; r++) {
    float2 o;
    o.x = fmaxf(sum2(acc[r][0]) + bv.x, 0.0f);
    o.y = fmaxf(sum2(acc[r][1]) + bv.y, 0.0f);
    ((float2*)(out + (row0 + warp * 8 + r) * HH + h * 64))[lane] = o;
  }
}

// ---------------------------------------------------------------------------
extern "C" void kernel_launch(void* const* d_in, const int* in_sizes, int n_in,
                              void* d_out, int out_size) {
  const float* z  = (const float*)d_in[0];
  const int*   P  = (const int*)  d_in[1];
  const float* W1 = (const float*)d_in[2];
  const float* b1 = (const float*)d_in[3];
  const float* W2 = (const float*)d_in[4];
  const float* b2 = (const float*)d_in[5];
  const float* Wu = (const float*)d_in[6];
  const float* bu = (const float*)d_in[7];
  float* out = (float*)d_out;

  (void)cudaFuncSetAttribute(lin_kernel, cudaFuncAttributeMaxDynamicSharedMemorySize, 98304);
  (void)cudaFuncSetAttribute(maxagg_kernel, cudaFuncAttributeMaxDynamicSharedMemorySize, 65536);
  (void)cudaFuncSetAttribute(out_kernel, cudaFuncAttributeMaxDynamicSharedMemorySize, 131072);

  pack_kernel<<<128, 256>>>(W1, W2, Wu);
  lin_kernel<<<dim3(BK / 64, 2), 512, 98304>>>(z, b1, b2);
  maxagg_kernel<<<dim3(KK / 16, BB), 512, 65536>>>(P);
  out_kernel<<<dim3(BK / 64, 2), 256, 131072>>>(z, bu, out);
}